// round 8
// baseline (speedup 1.0000x reference)
#include <cuda_runtime.h>
#include <stdint.h>

#define KE_HALF 7.199822675975274f   /* KE/2 */
#define MAX_NODES 131072
#define ZSCALE   2048.0f
#define PSCALE   8192.0f
#define YLUT_N   1024
#define YLUT_TMAX 16.0f
#define GLUT_N   512                 /* over L in [0.5, 1.5) */

// Packed per-node table: low16 = round(z*2048), high16 = round(z^p*d*8192).
__device__ uint32_t g_packed[MAX_NODES];
__device__ float    g_par[8];   // [0..3] = a_k (positive), [4..7] = normalized c_k

__device__ __forceinline__ float softplus_f(float x) {
    return fmaxf(x, 0.0f) + log1pf(__expf(-fabsf(x)));
}

// Streaming loads: evict-first, keep L1 for the node table.
__device__ __forceinline__ float4 ldcs4(const float4* p) {
    float4 v;
    asm("ld.global.cs.v4.f32 {%0,%1,%2,%3}, [%4];"
        : "=f"(v.x), "=f"(v.y), "=f"(v.z), "=f"(v.w) : "l"(p));
    return v;
}
__device__ __forceinline__ int4 ldcs4i(const int4* p) {
    int4 v;
    asm("ld.global.cs.v4.b32 {%0,%1,%2,%3}, [%4];"
        : "=r"(v.x), "=r"(v.y), "=r"(v.z), "=r"(v.w) : "l"(p));
    return v;
}

// Exact switch (reference formula), used only for LUT build.
__device__ __forceinline__ float switch_w(float L) {
    float c = L * (1.0f / 1.5f);
    if (c >= 1.0f) return 0.0f;
    float s1 = __expf(-1.0f / fmaxf(1.0f - c, 1e-12f));
    float s0 = __expf(-1.0f / fmaxf(c, 1e-12f));
    return s1 / (s1 + s0 + 1e-12f);
}

// Fused: zero output + per-node packing + (thread 0) param derivation.
__global__ void node_kernel(const float* __restrict__ z,
                            const float* __restrict__ p_raw,
                            const float* __restrict__ d_raw,
                            const float* __restrict__ a1, const float* __restrict__ a2,
                            const float* __restrict__ a3, const float* __restrict__ a4,
                            const float* __restrict__ c1, const float* __restrict__ c2,
                            const float* __restrict__ c3, const float* __restrict__ c4,
                            float* __restrict__ out, int n, int n_out) {
    int i = blockIdx.x * blockDim.x + threadIdx.x;
    if (i == 0) {
        float A1 = softplus_f(a1[0]), A2 = softplus_f(a2[0]);
        float A3 = softplus_f(a3[0]), A4 = softplus_f(a4[0]);
        float C1 = softplus_f(c1[0]), C2 = softplus_f(c2[0]);
        float C3 = softplus_f(c3[0]), C4 = softplus_f(c4[0]);
        float s = 1.0f / (C1 + C2 + C3 + C4);
        g_par[0] = A1; g_par[1] = A2; g_par[2] = A3; g_par[3] = A4;
        g_par[4] = C1 * s; g_par[5] = C2 * s; g_par[6] = C3 * s; g_par[7] = C4 * s;
    }
    if (i < n_out) out[i] = 0.0f;
    if (i < n) {
        float p = softplus_f(p_raw[0]);
        float d = softplus_f(d_raw[0]);
        float zi = z[i];
        float zpd = __powf(zi, p) * d;
        unsigned qz = __float2uint_rn(zi * ZSCALE);
        unsigned qp = __float2uint_rn(zpd * PSCALE);
        qz = qz > 65535u ? 65535u : qz;
        qp = qp > 65535u ? 65535u : qp;
        g_packed[i] = qz | (qp << 16);
    }
}

__global__ void __launch_bounds__(256, 8)
edge_kernel(const float* __restrict__ cut, const float* __restrict__ len,
            const int* __restrict__ snd, const int* __restrict__ rcv,
            float* __restrict__ out, int E) {
    // LUTs: (value, next-value - value) pairs for branch-free lerp.
    __shared__ float2 s_y[YLUT_N];   // y(t) over [0, 16]
    __shared__ float2 s_g[GLUT_N];   // w(L)/L over [0.5, 1.5)

    {
        const float A1 = g_par[0], A2 = g_par[1], A3 = g_par[2], A4 = g_par[3];
        const float C1 = g_par[4], C2 = g_par[5], C3 = g_par[6], C4 = g_par[7];
        for (int i = threadIdx.x; i < YLUT_N; i += blockDim.x) {
            float t0 = (float)i       * (YLUT_TMAX / YLUT_N);
            float t1 = (float)(i + 1) * (YLUT_TMAX / YLUT_N);
            float v0 = C1 * __expf(-A1 * t0) + C2 * __expf(-A2 * t0)
                     + C3 * __expf(-A3 * t0) + C4 * __expf(-A4 * t0);
            float v1 = C1 * __expf(-A1 * t1) + C2 * __expf(-A2 * t1)
                     + C3 * __expf(-A3 * t1) + C4 * __expf(-A4 * t1);
            s_y[i] = make_float2(v0, v1 - v0);
        }
        for (int i = threadIdx.x; i < GLUT_N; i += blockDim.x) {
            float L0 = 0.5f + (float)i       * (1.0f / GLUT_N);
            float L1 = 0.5f + (float)(i + 1) * (1.0f / GLUT_N);
            float v0 = switch_w(L0) / fmaxf(L0, 1e-6f);
            float v1 = switch_w(L1) / fmaxf(L1, 1e-6f);
            s_g[i] = make_float2(v0, v1 - v0);
        }
    }
    __syncthreads();

    int i4 = blockIdx.x * blockDim.x + threadIdx.x;
    long long base = (long long)i4 * 4;
    if (base >= E) return;

    float4 Lv, Cv; int4 Sv, Rv;
    if (base + 3 < E) {
        Lv = ldcs4(reinterpret_cast<const float4*>(len + base));
        Cv = ldcs4(reinterpret_cast<const float4*>(cut + base));
        Sv = ldcs4i(reinterpret_cast<const int4*>(snd + base));
        Rv = ldcs4i(reinterpret_cast<const int4*>(rcv + base));
    } else {
        float* lp = &Lv.x; float* cp = &Cv.x; int* sp = &Sv.x; int* rp = &Rv.x;
        for (int k = 0; k < 4; k++) {
            long long e = base + k;
            lp[k] = (e < E) ? len[e] : 2.0f;   // L >= 1.5 -> w == 0 -> no-op
            cp[k] = (e < E) ? cut[e] : 0.0f;
            sp[k] = (e < E) ? snd[e] : 0;
            rp[k] = (e < E) ? rcv[e] : 0;
        }
    }

    const float* lp = &Lv.x; const float* cp = &Cv.x;
    const int* sp = &Sv.x; const int* rp = &Rv.x;

    // ── Phase A: predicated gathers back-to-back (MLP=8, L1-cached table).
    uint32_t US[4], UR[4];
    bool act[4];
#pragma unroll
    for (int k = 0; k < 4; k++) {
        act[k] = lp[k] < 1.5f;                 // w == 0 exactly for L >= 1.5
        US[k] = 0; UR[k] = 0;
        if (act[k]) {
            US[k] = g_packed[sp[k]];           // (z_j | z_j^p*d)
            UR[k] = g_packed[rp[k]];           // (z_i | z_i^p*d)
        }
    }

    // ── Phase B: branch-free LUT math; result gated by predicated RED only.
#pragma unroll
    for (int k = 0; k < 4; k++) {
        float L = lp[k];

        // g = w(L)/L via LUT over [0.5, 1.5)
        float fg = (L - 0.5f) * (float)GLUT_N;
        fg = fminf(fmaxf(fg, 0.0f), (float)(GLUT_N - 1));
        int ig = (int)fg; float rg = fg - (float)ig;
        float2 G = s_g[ig];
        float g = fmaf(G.y, rg, G.x);

        unsigned qzs = US[k] & 0xffffu, qzr = UR[k] & 0xffffu;
        unsigned qsum = (US[k] >> 16) + (UR[k] >> 16);

        // y(t) via LUT, t = L * (z_i^p + z_j^p) * d
        float t = L * (float)qsum * (1.0f / PSCALE);
        float ft = t * ((float)YLUT_N / YLUT_TMAX);
        ft = fminf(ft, (float)(YLUT_N - 1));
        int it = (int)ft; float rt = ft - (float)it;
        float2 Y = s_y[it];
        float y = fmaf(Y.y, rt, Y.x);

        float num = (KE_HALF / (ZSCALE * ZSCALE)) * cp[k] * (float)(qzs * qzr);
        float val = num * g * y;

        if (act[k]) atomicAdd(out + rp[k], val);
    }
}

extern "C" void kernel_launch(void* const* d_in, const int* in_sizes, int n_in,
                              void* d_out, int out_size) {
    const float* z   = (const float*)d_in[0];
    const float* cut = (const float*)d_in[1];
    const int*   snd = (const int*)  d_in[2];
    const int*   rcv = (const int*)  d_in[3];
    const float* len = (const float*)d_in[4];

    int pb = n_in - 10;
    const float* a1 = (const float*)d_in[pb + 0];
    const float* a2 = (const float*)d_in[pb + 1];
    const float* a3 = (const float*)d_in[pb + 2];
    const float* a4 = (const float*)d_in[pb + 3];
    const float* c1 = (const float*)d_in[pb + 4];
    const float* c2 = (const float*)d_in[pb + 5];
    const float* c3 = (const float*)d_in[pb + 6];
    const float* c4 = (const float*)d_in[pb + 7];
    const float* pr = (const float*)d_in[pb + 8];
    const float* dr = (const float*)d_in[pb + 9];

    int N = in_sizes[0];
    int E = in_sizes[2];
    if (N > MAX_NODES) N = MAX_NODES;

    float* out = (float*)d_out;

    int cover = (N > out_size) ? N : out_size;
    node_kernel<<<(cover + 255) / 256, 256>>>(z, pr, dr, a1, a2, a3, a4,
                                              c1, c2, c3, c4, out, N, out_size);

    int n4 = (E + 3) / 4;
    edge_kernel<<<(n4 + 255) / 256, 256>>>(cut, len, snd, rcv, out, E);
}

// round 9
// speedup vs baseline: 1.2406x; 1.2406x over previous
#include <cuda_runtime.h>
#include <stdint.h>

#define KE_HALF 7.199822675975274f   /* KE/2 */
#define MAX_NODES 131072
#define ZSCALE   2048.0f
#define PSCALE   8192.0f
#define YLUT_N   1024
#define YLUT_TMAX 16.0f
#define GLUT_N   512                 /* over L in [0.5, 1.5) */
#define LUT_TOTAL (YLUT_N + GLUT_N)

// Packed per-node table: low16 = round(z*2048), high16 = round(z^p*d*8192).
__device__ uint32_t g_packed[MAX_NODES];
// Prebuilt LUT: [0,1024) = y(t) over [0,16]; [1024,1536) = w(L)/L over [0.5,1.5).
// Each entry = (value, next - value) for branch-free lerp.
__device__ float2   g_lut[LUT_TOTAL];

__device__ __forceinline__ float softplus_f(float x) {
    return fmaxf(x, 0.0f) + log1pf(__expf(-fabsf(x)));
}

// Streaming loads: evict-first, keep L1 for the node table.
__device__ __forceinline__ float4 ldcs4(const float4* p) {
    float4 v;
    asm("ld.global.cs.v4.f32 {%0,%1,%2,%3}, [%4];"
        : "=f"(v.x), "=f"(v.y), "=f"(v.z), "=f"(v.w) : "l"(p));
    return v;
}
__device__ __forceinline__ int4 ldcs4i(const int4* p) {
    int4 v;
    asm("ld.global.cs.v4.b32 {%0,%1,%2,%3}, [%4];"
        : "=r"(v.x), "=r"(v.y), "=r"(v.z), "=r"(v.w) : "l"(p));
    return v;
}

// Exact switch (reference formula), used only for LUT build.
__device__ __forceinline__ float switch_w(float L) {
    float c = L * (1.0f / 1.5f);
    if (c >= 1.0f) return 0.0f;
    float s1 = __expf(-1.0f / fmaxf(1.0f - c, 1e-12f));
    float s0 = __expf(-1.0f / fmaxf(c, 1e-12f));
    return s1 / (s1 + s0 + 1e-12f);
}

// Fused: zero output + per-node packing + one-time LUT build (threads < 1536).
__global__ void node_kernel(const float* __restrict__ z,
                            const float* __restrict__ p_raw,
                            const float* __restrict__ d_raw,
                            const float* __restrict__ a1, const float* __restrict__ a2,
                            const float* __restrict__ a3, const float* __restrict__ a4,
                            const float* __restrict__ c1, const float* __restrict__ c2,
                            const float* __restrict__ c3, const float* __restrict__ c4,
                            float* __restrict__ out, int n, int n_out) {
    int i = blockIdx.x * blockDim.x + threadIdx.x;

    if (i < LUT_TOTAL) {
        // Derive params redundantly per LUT thread (1536 threads, negligible).
        float A1 = softplus_f(a1[0]), A2 = softplus_f(a2[0]);
        float A3 = softplus_f(a3[0]), A4 = softplus_f(a4[0]);
        float C1 = softplus_f(c1[0]), C2 = softplus_f(c2[0]);
        float C3 = softplus_f(c3[0]), C4 = softplus_f(c4[0]);
        float s = 1.0f / (C1 + C2 + C3 + C4);
        C1 *= s; C2 *= s; C3 *= s; C4 *= s;
        if (i < YLUT_N) {
            float t0 = (float)i       * (YLUT_TMAX / YLUT_N);
            float t1 = (float)(i + 1) * (YLUT_TMAX / YLUT_N);
            float v0 = C1 * __expf(-A1 * t0) + C2 * __expf(-A2 * t0)
                     + C3 * __expf(-A3 * t0) + C4 * __expf(-A4 * t0);
            float v1 = C1 * __expf(-A1 * t1) + C2 * __expf(-A2 * t1)
                     + C3 * __expf(-A3 * t1) + C4 * __expf(-A4 * t1);
            g_lut[i] = make_float2(v0, v1 - v0);
        } else {
            int j = i - YLUT_N;
            float L0 = 0.5f + (float)j       * (1.0f / GLUT_N);
            float L1 = 0.5f + (float)(j + 1) * (1.0f / GLUT_N);
            float v0 = switch_w(L0) / fmaxf(L0, 1e-6f);
            float v1 = switch_w(L1) / fmaxf(L1, 1e-6f);
            g_lut[i] = make_float2(v0, v1 - v0);
        }
    }

    if (i < n_out) out[i] = 0.0f;
    if (i < n) {
        float p = softplus_f(p_raw[0]);
        float d = softplus_f(d_raw[0]);
        float zi = z[i];
        float zpd = __powf(zi, p) * d;
        unsigned qz = __float2uint_rn(zi * ZSCALE);
        unsigned qp = __float2uint_rn(zpd * PSCALE);
        qz = qz > 65535u ? 65535u : qz;
        qp = qp > 65535u ? 65535u : qp;
        g_packed[i] = qz | (qp << 16);
    }
}

__global__ void __launch_bounds__(256, 8)
edge_kernel(const float* __restrict__ cut, const float* __restrict__ len,
            const int* __restrict__ snd, const int* __restrict__ rcv,
            float* __restrict__ out, int E) {
    __shared__ float2 s_lut[LUT_TOTAL];

    // Copy prebuilt LUT global -> smem (12KB, uint4-vectorized: 3 per thread).
    {
        const uint4* src = reinterpret_cast<const uint4*>(g_lut);
        uint4* dst = reinterpret_cast<uint4*>(s_lut);
        const int n16 = LUT_TOTAL * 8 / 16;   // 768
        for (int i = threadIdx.x; i < n16; i += blockDim.x) dst[i] = src[i];
    }
    __syncthreads();
    const float2* s_y = s_lut;
    const float2* s_g = s_lut + YLUT_N;

    int i4 = blockIdx.x * blockDim.x + threadIdx.x;
    long long base = (long long)i4 * 4;
    if (base >= E) return;

    float4 Lv, Cv; int4 Sv, Rv;
    if (base + 3 < E) {
        Lv = ldcs4(reinterpret_cast<const float4*>(len + base));
        Cv = ldcs4(reinterpret_cast<const float4*>(cut + base));
        Sv = ldcs4i(reinterpret_cast<const int4*>(snd + base));
        Rv = ldcs4i(reinterpret_cast<const int4*>(rcv + base));
    } else {
        float* lp = &Lv.x; float* cp = &Cv.x; int* sp = &Sv.x; int* rp = &Rv.x;
        for (int k = 0; k < 4; k++) {
            long long e = base + k;
            lp[k] = (e < E) ? len[e] : 2.0f;   // L >= 1.5 -> w == 0 -> no-op
            cp[k] = (e < E) ? cut[e] : 0.0f;
            sp[k] = (e < E) ? snd[e] : 0;
            rp[k] = (e < E) ? rcv[e] : 0;
        }
    }

    const float* lp = &Lv.x; const float* cp = &Cv.x;
    const int* sp = &Sv.x; const int* rp = &Rv.x;

    // ── Phase A: predicated gathers back-to-back (MLP=8, L1-cached table).
    uint32_t US[4], UR[4];
    bool act[4];
#pragma unroll
    for (int k = 0; k < 4; k++) {
        act[k] = lp[k] < 1.5f;                 // w == 0 exactly for L >= 1.5
        US[k] = 0; UR[k] = 0;
        if (act[k]) {
            US[k] = g_packed[sp[k]];           // (z_j | z_j^p*d)
            UR[k] = g_packed[rp[k]];           // (z_i | z_i^p*d)
        }
    }

    // ── Phase B: branch-free LUT math; gated only by the predicated RED.
#pragma unroll
    for (int k = 0; k < 4; k++) {
        float L = lp[k];

        // g = w(L)/L via LUT over [0.5, 1.5)
        float fg = (L - 0.5f) * (float)GLUT_N;
        fg = fminf(fmaxf(fg, 0.0f), (float)(GLUT_N - 1));
        int ig = (int)fg; float rg = fg - (float)ig;
        float2 G = s_g[ig];
        float g = fmaf(G.y, rg, G.x);

        unsigned qzs = US[k] & 0xffffu, qzr = UR[k] & 0xffffu;
        unsigned qsum = (US[k] >> 16) + (UR[k] >> 16);

        // y(t) via LUT, t = L * (z_i^p + z_j^p) * d
        float t = L * (float)qsum * (1.0f / PSCALE);
        float ft = t * ((float)YLUT_N / YLUT_TMAX);
        ft = fminf(ft, (float)(YLUT_N - 1));
        int it = (int)ft; float rt = ft - (float)it;
        float2 Y = s_y[it];
        float y = fmaf(Y.y, rt, Y.x);

        float num = (KE_HALF / (ZSCALE * ZSCALE)) * cp[k] * (float)(qzs * qzr);
        float val = num * g * y;

        if (act[k]) atomicAdd(out + rp[k], val);
    }
}

extern "C" void kernel_launch(void* const* d_in, const int* in_sizes, int n_in,
                              void* d_out, int out_size) {
    const float* z   = (const float*)d_in[0];
    const float* cut = (const float*)d_in[1];
    const int*   snd = (const int*)  d_in[2];
    const int*   rcv = (const int*)  d_in[3];
    const float* len = (const float*)d_in[4];

    int pb = n_in - 10;
    const float* a1 = (const float*)d_in[pb + 0];
    const float* a2 = (const float*)d_in[pb + 1];
    const float* a3 = (const float*)d_in[pb + 2];
    const float* a4 = (const float*)d_in[pb + 3];
    const float* c1 = (const float*)d_in[pb + 4];
    const float* c2 = (const float*)d_in[pb + 5];
    const float* c3 = (const float*)d_in[pb + 6];
    const float* c4 = (const float*)d_in[pb + 7];
    const float* pr = (const float*)d_in[pb + 8];
    const float* dr = (const float*)d_in[pb + 9];

    int N = in_sizes[0];
    int E = in_sizes[2];
    if (N > MAX_NODES) N = MAX_NODES;

    float* out = (float*)d_out;

    int cover = (N > out_size) ? N : out_size;
    node_kernel<<<(cover + 255) / 256, 256>>>(z, pr, dr, a1, a2, a3, a4,
                                              c1, c2, c3, c4, out, N, out_size);

    int n4 = (E + 3) / 4;
    edge_kernel<<<(n4 + 255) / 256, 256>>>(cut, len, snd, rcv, out, E);
}

// round 10
// speedup vs baseline: 1.5162x; 1.2221x over previous
#include <cuda_runtime.h>
#include <stdint.h>

#define KE_HALF 7.199822675975274f   /* KE/2 */
#define LOG2E   1.4426950408889634f
#define MAX_NODES 131072
#define ZSCALE   2048.0f

// 2B per node: qz = round(z * 2048). 195KB -> entire table is L1-resident.
__device__ uint16_t g_ztab[MAX_NODES];
__device__ float    g_par[12];  // [0..3]=-a_k*log2e, [4..7]=c_k norm, [8]=p, [9]=d*2^(-11p)

__device__ __forceinline__ float softplus_f(float x) {
    return fmaxf(x, 0.0f) + log1pf(__expf(-fabsf(x)));
}
__device__ __forceinline__ float ex2f(float x) {
    float y; asm("ex2.approx.ftz.f32 %0, %1;" : "=f"(y) : "f"(x)); return y;
}
__device__ __forceinline__ float lg2f(float x) {
    float y; asm("lg2.approx.ftz.f32 %0, %1;" : "=f"(y) : "f"(x)); return y;
}

// Streaming loads: evict-first so they don't displace the node table in L1.
__device__ __forceinline__ float4 ldcs4(const float4* p) {
    float4 v;
    asm("ld.global.cs.v4.f32 {%0,%1,%2,%3}, [%4];"
        : "=f"(v.x), "=f"(v.y), "=f"(v.z), "=f"(v.w) : "l"(p));
    return v;
}
__device__ __forceinline__ int4 ldcs4i(const int4* p) {
    int4 v;
    asm("ld.global.cs.v4.b32 {%0,%1,%2,%3}, [%4];"
        : "=r"(v.x), "=r"(v.y), "=r"(v.z), "=r"(v.w) : "l"(p));
    return v;
}

// Fused: zero output + per-node 16-bit quantization + (thread 0) param derivation.
__global__ void node_kernel(const float* __restrict__ z,
                            const float* __restrict__ p_raw,
                            const float* __restrict__ d_raw,
                            const float* __restrict__ a1, const float* __restrict__ a2,
                            const float* __restrict__ a3, const float* __restrict__ a4,
                            const float* __restrict__ c1, const float* __restrict__ c2,
                            const float* __restrict__ c3, const float* __restrict__ c4,
                            float* __restrict__ out, int n, int n_out) {
    int i = blockIdx.x * blockDim.x + threadIdx.x;
    if (i == 0) {
        float A1 = softplus_f(a1[0]), A2 = softplus_f(a2[0]);
        float A3 = softplus_f(a3[0]), A4 = softplus_f(a4[0]);
        float C1 = softplus_f(c1[0]), C2 = softplus_f(c2[0]);
        float C3 = softplus_f(c3[0]), C4 = softplus_f(c4[0]);
        float s = 1.0f / (C1 + C2 + C3 + C4);
        float P = softplus_f(p_raw[0]);
        float D = softplus_f(d_raw[0]);
        g_par[0] = -A1 * LOG2E; g_par[1] = -A2 * LOG2E;
        g_par[2] = -A3 * LOG2E; g_par[3] = -A4 * LOG2E;
        g_par[4] = C1 * s; g_par[5] = C2 * s; g_par[6] = C3 * s; g_par[7] = C4 * s;
        g_par[8] = P;
        g_par[9] = D * ex2f(-11.0f * P);   // z^p*d = DS * 2^(p*lg2(qz)), qz = z*2^11
    }
    if (i < n_out) out[i] = 0.0f;
    if (i < n) {
        unsigned q = __float2uint_rn(z[i] * ZSCALE);
        g_ztab[i] = (uint16_t)(q > 65535u ? 65535u : q);
    }
}

__global__ void __launch_bounds__(256, 8)
edge_kernel(const float* __restrict__ cut, const float* __restrict__ len,
            const int* __restrict__ snd, const int* __restrict__ rcv,
            float* __restrict__ out, int E) {
    int i4 = blockIdx.x * blockDim.x + threadIdx.x;
    long long base = (long long)i4 * 4;
    if (base >= E) return;

    float4 Lv, Cv; int4 Sv, Rv;
    if (base + 3 < E) {
        Lv = ldcs4(reinterpret_cast<const float4*>(len + base));
        Cv = ldcs4(reinterpret_cast<const float4*>(cut + base));
        Sv = ldcs4i(reinterpret_cast<const int4*>(snd + base));
        Rv = ldcs4i(reinterpret_cast<const int4*>(rcv + base));
    } else {
        float* lp = &Lv.x; float* cp = &Cv.x; int* sp = &Sv.x; int* rp = &Rv.x;
        for (int k = 0; k < 4; k++) {
            long long e = base + k;
            lp[k] = (e < E) ? len[e] : 2.0f;   // L >= 1.5 -> w == 0 -> no-op
            cp[k] = (e < E) ? cut[e] : 0.0f;
            sp[k] = (e < E) ? snd[e] : 0;
            rp[k] = (e < E) ? rcv[e] : 0;
        }
    }

    const float* lp = &Lv.x; const float* cp = &Cv.x;
    const int* sp = &Sv.x; const int* rp = &Rv.x;

    // ── Phase A: predicated 2B gathers back-to-back (MLP=8, table L1-resident).
    unsigned QS[4], QR[4];
    bool act[4];
#pragma unroll
    for (int k = 0; k < 4; k++) {
        act[k] = lp[k] < 1.5f;                 // w == 0 exactly for L >= 1.5
        QS[k] = 2048; QR[k] = 2048;
        if (act[k]) {
            QS[k] = (unsigned)g_ztab[sp[k]];
            QR[k] = (unsigned)g_ztab[rp[k]];
        }
    }

    const float b1 = g_par[0], b2 = g_par[1], b3 = g_par[2], b4 = g_par[3];
    const float c1 = g_par[4], c2 = g_par[5], c3 = g_par[6], c4 = g_par[7];
    const float P  = g_par[8], DS = g_par[9];

    // ── Phase B: math + fire-and-forget atomics.
#pragma unroll
    for (int k = 0; k < 4; k++) {
        if (!act[k]) continue;
        float L = lp[k];
        float cc = L * (1.0f / 1.5f);

        // w*x*0.5 = KE_HALF*cut*zi*zj / ((1 + 2^fl) * L),  fl = (2cc-1)*log2e/(cc(1-cc))
        float om = 1.0f - cc;
        float fl = __fdividef((cc + cc - 1.0f) * LOG2E, cc * om);
        float ef = ex2f(fl);
        float D  = (1.0f + ef) * fmaxf(L, 1e-6f);

        // z^p*d = DS * 2^(p * lg2(qz));   zi*zj = (qs*qr) / 2048^2
        float zps = ex2f(P * lg2f((float)QS[k]));
        float zpr = ex2f(P * lg2f((float)QR[k]));
        float zz  = (float)(QS[k] * QR[k]);          // < 2^32 (qz <= 61440)

        float num = (KE_HALF / (ZSCALE * ZSCALE)) * cp[k] * zz;
        float t   = L * DS * (zps + zpr);            // rzd
        float y = c1 * ex2f(b1 * t) + c2 * ex2f(b2 * t)
                + c3 * ex2f(b3 * t) + c4 * ex2f(b4 * t);

        atomicAdd(out + rp[k], __fdividef(num * y, D));
    }
}

extern "C" void kernel_launch(void* const* d_in, const int* in_sizes, int n_in,
                              void* d_out, int out_size) {
    const float* z   = (const float*)d_in[0];
    const float* cut = (const float*)d_in[1];
    const int*   snd = (const int*)  d_in[2];
    const int*   rcv = (const int*)  d_in[3];
    const float* len = (const float*)d_in[4];

    int pb = n_in - 10;
    const float* a1 = (const float*)d_in[pb + 0];
    const float* a2 = (const float*)d_in[pb + 1];
    const float* a3 = (const float*)d_in[pb + 2];
    const float* a4 = (const float*)d_in[pb + 3];
    const float* c1 = (const float*)d_in[pb + 4];
    const float* c2 = (const float*)d_in[pb + 5];
    const float* c3 = (const float*)d_in[pb + 6];
    const float* c4 = (const float*)d_in[pb + 7];
    const float* pr = (const float*)d_in[pb + 8];
    const float* dr = (const float*)d_in[pb + 9];

    int N = in_sizes[0];
    int E = in_sizes[2];
    if (N > MAX_NODES) N = MAX_NODES;

    float* out = (float*)d_out;

    int cover = (N > out_size) ? N : out_size;
    node_kernel<<<(cover + 255) / 256, 256>>>(z, pr, dr, a1, a2, a3, a4,
                                              c1, c2, c3, c4, out, N, out_size);

    int n4 = (E + 3) / 4;
    edge_kernel<<<(n4 + 255) / 256, 256>>>(cut, len, snd, rcv, out, E);
}

// round 11
// speedup vs baseline: 1.5286x; 1.0082x over previous
#include <cuda_runtime.h>
#include <stdint.h>

#define KE_HALF 7.199822675975274f   /* KE/2 */
#define LOG2E   1.4426950408889634f
#define MAX_NODES 131072
#define ZSCALE   2048.0f
#define YLUT_N   1024
#define YLUT_TMAX 16.0f
#define GLUT_N   512                 /* over L in [0.5, 1.5) */
#define LUT_TOTAL (YLUT_N + GLUT_N)
#define LUT_BYTES (LUT_TOTAL * 8)    /* 12288 */
#define SMEM_CAP_NODES 104000        /* 208000B table + 12288B LUT = 215.1KB */

// 2B per node: qz = round(z * 2048).
__device__ uint16_t g_ztab[MAX_NODES];
// Prebuilt LUTs: [0,1024) y(t) over [0,16]; [1024,1536) w(L)/L over [0.5,1.5).
__device__ float2   g_lut[LUT_TOTAL];
__device__ float    g_par[4];        // [0]=p, [1]=d*2^(-11p)

__device__ __forceinline__ float softplus_f(float x) {
    return fmaxf(x, 0.0f) + log1pf(__expf(-fabsf(x)));
}
__device__ __forceinline__ float ex2f(float x) {
    float y; asm("ex2.approx.ftz.f32 %0, %1;" : "=f"(y) : "f"(x)); return y;
}
__device__ __forceinline__ float lg2f(float x) {
    float y; asm("lg2.approx.ftz.f32 %0, %1;" : "=f"(y) : "f"(x)); return y;
}

__device__ __forceinline__ float4 ldcs4(const float4* p) {
    float4 v;
    asm("ld.global.cs.v4.f32 {%0,%1,%2,%3}, [%4];"
        : "=f"(v.x), "=f"(v.y), "=f"(v.z), "=f"(v.w) : "l"(p));
    return v;
}
__device__ __forceinline__ int4 ldcs4i(const int4* p) {
    int4 v;
    asm("ld.global.cs.v4.b32 {%0,%1,%2,%3}, [%4];"
        : "=r"(v.x), "=r"(v.y), "=r"(v.z), "=r"(v.w) : "l"(p));
    return v;
}

__device__ __forceinline__ float switch_w(float L) {
    float c = L * (1.0f / 1.5f);
    if (c >= 1.0f) return 0.0f;
    float s1 = __expf(-1.0f / fmaxf(1.0f - c, 1e-12f));
    float s0 = __expf(-1.0f / fmaxf(c, 1e-12f));
    return s1 / (s1 + s0 + 1e-12f);
}

// Fused: zero output + 16-bit node packing + LUT build (threads < 1536) + params.
__global__ void node_kernel(const float* __restrict__ z,
                            const float* __restrict__ p_raw,
                            const float* __restrict__ d_raw,
                            const float* __restrict__ a1, const float* __restrict__ a2,
                            const float* __restrict__ a3, const float* __restrict__ a4,
                            const float* __restrict__ c1, const float* __restrict__ c2,
                            const float* __restrict__ c3, const float* __restrict__ c4,
                            float* __restrict__ out, int n, int n_out) {
    int i = blockIdx.x * blockDim.x + threadIdx.x;

    if (i < LUT_TOTAL) {
        float A1 = softplus_f(a1[0]), A2 = softplus_f(a2[0]);
        float A3 = softplus_f(a3[0]), A4 = softplus_f(a4[0]);
        float C1 = softplus_f(c1[0]), C2 = softplus_f(c2[0]);
        float C3 = softplus_f(c3[0]), C4 = softplus_f(c4[0]);
        float s = 1.0f / (C1 + C2 + C3 + C4);
        C1 *= s; C2 *= s; C3 *= s; C4 *= s;
        if (i < YLUT_N) {
            float t0 = (float)i       * (YLUT_TMAX / YLUT_N);
            float t1 = (float)(i + 1) * (YLUT_TMAX / YLUT_N);
            float v0 = C1 * __expf(-A1 * t0) + C2 * __expf(-A2 * t0)
                     + C3 * __expf(-A3 * t0) + C4 * __expf(-A4 * t0);
            float v1 = C1 * __expf(-A1 * t1) + C2 * __expf(-A2 * t1)
                     + C3 * __expf(-A3 * t1) + C4 * __expf(-A4 * t1);
            g_lut[i] = make_float2(v0, v1 - v0);
        } else {
            int j = i - YLUT_N;
            float L0 = 0.5f + (float)j       * (1.0f / GLUT_N);
            float L1 = 0.5f + (float)(j + 1) * (1.0f / GLUT_N);
            float v0 = switch_w(L0) / fmaxf(L0, 1e-6f);
            float v1 = switch_w(L1) / fmaxf(L1, 1e-6f);
            g_lut[i] = make_float2(v0, v1 - v0);
        }
    }
    if (i == 0) {
        float P = softplus_f(p_raw[0]);
        float D = softplus_f(d_raw[0]);
        g_par[0] = P;
        g_par[1] = D * ex2f(-11.0f * P);   // z^p*d = DS * 2^(p*lg2(qz)), qz = z*2^11
    }
    if (i < n_out) out[i] = 0.0f;
    if (i < n) {
        unsigned q = __float2uint_rn(z[i] * ZSCALE);
        g_ztab[i] = (uint16_t)(q > 65535u ? 65535u : q);
    }
}

__global__ void __launch_bounds__(1024, 1)
edge_kernel(const float* __restrict__ cut, const float* __restrict__ len,
            const int* __restrict__ snd, const int* __restrict__ rcv,
            float* __restrict__ out, int E, int tn, int zb) {
    extern __shared__ __align__(16) char sm[];
    uint16_t* s_z = (uint16_t*)sm;
    float2*   s_y = (float2*)(sm + zb);
    float2*   s_g = s_y + YLUT_N;

    // Stage: node table (zb bytes) + LUTs (12288B), uint4-vectorized.
    {
        uint4* dst = (uint4*)sm;
        const uint4* src = (const uint4*)g_ztab;
        int nv = zb >> 4;
        for (int i = threadIdx.x; i < nv; i += 1024) dst[i] = src[i];
        uint4* dl = (uint4*)(sm + zb);
        const uint4* sl = (const uint4*)g_lut;
        for (int i = threadIdx.x; i < (LUT_BYTES >> 4); i += 1024) dl[i] = sl[i];
    }
    __syncthreads();

    const float P  = g_par[0], DS = g_par[1];

    const int nq = (E + 3) >> 2;
    const int stride = gridDim.x * 1024;

    for (int q = blockIdx.x * 1024 + threadIdx.x; q < nq; q += stride) {
        int base = q << 2;

        float4 Lv, Cv; int4 Sv, Rv;
        if (base + 3 < E) {
            Lv = ldcs4((const float4*)(len + base));
            Cv = ldcs4((const float4*)(cut + base));
            Sv = ldcs4i((const int4*)(snd + base));
            Rv = ldcs4i((const int4*)(rcv + base));
        } else {
            float* lp = &Lv.x; float* cp = &Cv.x; int* sp = &Sv.x; int* rp = &Rv.x;
            for (int k = 0; k < 4; k++) {
                int e = base + k;
                lp[k] = (e < E) ? len[e] : 2.0f;   // L >= 1.5 -> w == 0 -> no-op
                cp[k] = (e < E) ? cut[e] : 0.0f;
                sp[k] = (e < E) ? snd[e] : 0;
                rp[k] = (e < E) ? rcv[e] : 0;
            }
        }

        const float* lp = &Lv.x; const float* cp = &Cv.x;
        const int* sp = &Sv.x; const int* rp = &Rv.x;

        // ── Phase A: unconditional gathers (LDS; indices always valid).
        float QS[4], QR[4];
#pragma unroll
        for (int k = 0; k < 4; k++) {
            int s = sp[k], r = rp[k];
            unsigned qs = (s < tn) ? (unsigned)s_z[s] : (unsigned)g_ztab[s];
            unsigned qr = (r < tn) ? (unsigned)s_z[r] : (unsigned)g_ztab[r];
            QS[k] = (float)qs;
            QR[k] = (float)qr;
        }

        // ── Phase B: branch-free LUT + 4-MUFU math; only the RED is predicated.
#pragma unroll
        for (int k = 0; k < 4; k++) {
            float L = lp[k];

            // g = w(L)/L via LUT over [0.5, 1.5)
            float fg = (L - 0.5f) * (float)GLUT_N;
            fg = fminf(fmaxf(fg, 0.0f), (float)(GLUT_N - 1));
            int ig = (int)fg; float rg = fg - (float)ig;
            float2 G = s_g[ig];
            float g = fmaf(G.y, rg, G.x);

            // t = L * DS * (2^(P*lg2 qs) + 2^(P*lg2 qr))
            float zps = ex2f(P * lg2f(QS[k]));
            float zpr = ex2f(P * lg2f(QR[k]));
            float t = L * DS * (zps + zpr);

            // y(t) via LUT over [0, 16]
            float ft = t * ((float)YLUT_N / YLUT_TMAX);
            ft = fminf(fmaxf(ft, 0.0f), (float)(YLUT_N - 1));
            int it = (int)ft; float rt = ft - (float)it;
            float2 Y = s_y[it];
            float y = fmaf(Y.y, rt, Y.x);

            float num = (KE_HALF / (ZSCALE * ZSCALE)) * cp[k] * (QS[k] * QR[k]);
            float val = num * g * y;

            if (L < 1.5f) atomicAdd(out + rp[k], val);
        }
    }
}

extern "C" void kernel_launch(void* const* d_in, const int* in_sizes, int n_in,
                              void* d_out, int out_size) {
    const float* z   = (const float*)d_in[0];
    const float* cut = (const float*)d_in[1];
    const int*   snd = (const int*)  d_in[2];
    const int*   rcv = (const int*)  d_in[3];
    const float* len = (const float*)d_in[4];

    int pb = n_in - 10;
    const float* a1 = (const float*)d_in[pb + 0];
    const float* a2 = (const float*)d_in[pb + 1];
    const float* a3 = (const float*)d_in[pb + 2];
    const float* a4 = (const float*)d_in[pb + 3];
    const float* c1 = (const float*)d_in[pb + 4];
    const float* c2 = (const float*)d_in[pb + 5];
    const float* c3 = (const float*)d_in[pb + 6];
    const float* c4 = (const float*)d_in[pb + 7];
    const float* pr = (const float*)d_in[pb + 8];
    const float* dr = (const float*)d_in[pb + 9];

    int N = in_sizes[0];
    int E = in_sizes[2];
    if (N > MAX_NODES) N = MAX_NODES;

    float* out = (float*)d_out;

    int cover = (N > out_size) ? N : out_size;
    node_kernel<<<(cover + 255) / 256, 256>>>(z, pr, dr, a1, a2, a3, a4,
                                              c1, c2, c3, c4, out, N, out_size);

    int tn = (N < SMEM_CAP_NODES) ? N : SMEM_CAP_NODES;
    int zb = (tn * 2 + 15) & ~15;          // staged table bytes, 16B-aligned
    int smem = zb + LUT_BYTES;

    static int nsm = 0;
    if (nsm == 0) {
        cudaDeviceGetAttribute(&nsm, cudaDevAttrMultiProcessorCount, 0);
        if (nsm <= 0) nsm = 148;
        cudaFuncSetAttribute(edge_kernel,
                             cudaFuncAttributeMaxDynamicSharedMemorySize,
                             SMEM_CAP_NODES * 2 + 16 + LUT_BYTES);
    }
    edge_kernel<<<nsm, 1024, smem>>>(cut, len, snd, rcv, out, E, tn, zb);
}

// round 12
// speedup vs baseline: 1.6212x; 1.0606x over previous
#include <cuda_runtime.h>
#include <stdint.h>

#define KE_HALF 7.199822675975274f   /* KE/2 */
#define LOG2E   1.4426950408889634f
#define MAX_NODES 131072
#define ZSCALE   2048.0f
#define YLUT_N   1024
#define YLUT_TMAX 16.0f
#define GLUT_N   512                 /* over L in [0.5, 1.5) */
#define LUT_TOTAL (YLUT_N + GLUT_N)
#define LUT_BYTES (LUT_TOTAL * 8)    /* 12288 */
#define SMEM_CAP_NODES 104000        /* 208000B table + 12288B LUT = 215.1KB */
#define NTHREADS 768

// 2B per node: qz = round(z * 2048).
__device__ uint16_t g_ztab[MAX_NODES];
// Prebuilt LUTs: [0,1024) y(t) over [0,16]; [1024,1536) w(L)/L over [0.5,1.5).
__device__ float2   g_lut[LUT_TOTAL];
__device__ float    g_par[4];        // [0]=p, [1]=d*2^(-11p)

__device__ __forceinline__ float softplus_f(float x) {
    return fmaxf(x, 0.0f) + log1pf(__expf(-fabsf(x)));
}
__device__ __forceinline__ float ex2f(float x) {
    float y; asm("ex2.approx.ftz.f32 %0, %1;" : "=f"(y) : "f"(x)); return y;
}
__device__ __forceinline__ float lg2f(float x) {
    float y; asm("lg2.approx.ftz.f32 %0, %1;" : "=f"(y) : "f"(x)); return y;
}

__device__ __forceinline__ float4 ldcs4(const float4* p) {
    float4 v;
    asm("ld.global.cs.v4.f32 {%0,%1,%2,%3}, [%4];"
        : "=f"(v.x), "=f"(v.y), "=f"(v.z), "=f"(v.w) : "l"(p));
    return v;
}
__device__ __forceinline__ int4 ldcs4i(const int4* p) {
    int4 v;
    asm("ld.global.cs.v4.b32 {%0,%1,%2,%3}, [%4];"
        : "=r"(v.x), "=r"(v.y), "=r"(v.z), "=r"(v.w) : "l"(p));
    return v;
}

__device__ __forceinline__ float switch_w(float L) {
    float c = L * (1.0f / 1.5f);
    if (c >= 1.0f) return 0.0f;
    float s1 = __expf(-1.0f / fmaxf(1.0f - c, 1e-12f));
    float s0 = __expf(-1.0f / fmaxf(c, 1e-12f));
    return s1 / (s1 + s0 + 1e-12f);
}

// Load one edge-quad (with scalar tail fallback).
__device__ __forceinline__ void load_quad(int base, int E,
                                          const float* cut, const float* len,
                                          const int* snd, const int* rcv,
                                          float4& Lv, float4& Cv, int4& Sv, int4& Rv) {
    if (base + 3 < E) {
        Lv = ldcs4((const float4*)(len + base));
        Cv = ldcs4((const float4*)(cut + base));
        Sv = ldcs4i((const int4*)(snd + base));
        Rv = ldcs4i((const int4*)(rcv + base));
    } else {
        float* lp = &Lv.x; float* cp = &Cv.x; int* sp = &Sv.x; int* rp = &Rv.x;
        for (int k = 0; k < 4; k++) {
            int e = base + k;
            lp[k] = (e < E) ? len[e] : 2.0f;   // L >= 1.5 -> w == 0 -> no-op
            cp[k] = (e < E) ? cut[e] : 0.0f;
            sp[k] = (e < E) ? snd[e] : 0;
            rp[k] = (e < E) ? rcv[e] : 0;
        }
    }
}

// Fused: zero output + 16-bit node packing + LUT build (threads < 1536) + params.
__global__ void node_kernel(const float* __restrict__ z,
                            const float* __restrict__ p_raw,
                            const float* __restrict__ d_raw,
                            const float* __restrict__ a1, const float* __restrict__ a2,
                            const float* __restrict__ a3, const float* __restrict__ a4,
                            const float* __restrict__ c1, const float* __restrict__ c2,
                            const float* __restrict__ c3, const float* __restrict__ c4,
                            float* __restrict__ out, int n, int n_out) {
    int i = blockIdx.x * blockDim.x + threadIdx.x;

    if (i < LUT_TOTAL) {
        float A1 = softplus_f(a1[0]), A2 = softplus_f(a2[0]);
        float A3 = softplus_f(a3[0]), A4 = softplus_f(a4[0]);
        float C1 = softplus_f(c1[0]), C2 = softplus_f(c2[0]);
        float C3 = softplus_f(c3[0]), C4 = softplus_f(c4[0]);
        float s = 1.0f / (C1 + C2 + C3 + C4);
        C1 *= s; C2 *= s; C3 *= s; C4 *= s;
        if (i < YLUT_N) {
            float t0 = (float)i       * (YLUT_TMAX / YLUT_N);
            float t1 = (float)(i + 1) * (YLUT_TMAX / YLUT_N);
            float v0 = C1 * __expf(-A1 * t0) + C2 * __expf(-A2 * t0)
                     + C3 * __expf(-A3 * t0) + C4 * __expf(-A4 * t0);
            float v1 = C1 * __expf(-A1 * t1) + C2 * __expf(-A2 * t1)
                     + C3 * __expf(-A3 * t1) + C4 * __expf(-A4 * t1);
            g_lut[i] = make_float2(v0, v1 - v0);
        } else {
            int j = i - YLUT_N;
            float L0 = 0.5f + (float)j       * (1.0f / GLUT_N);
            float L1 = 0.5f + (float)(j + 1) * (1.0f / GLUT_N);
            float v0 = switch_w(L0) / fmaxf(L0, 1e-6f);
            float v1 = switch_w(L1) / fmaxf(L1, 1e-6f);
            g_lut[i] = make_float2(v0, v1 - v0);
        }
    }
    if (i == 0) {
        float P = softplus_f(p_raw[0]);
        float D = softplus_f(d_raw[0]);
        g_par[0] = P;
        g_par[1] = D * ex2f(-11.0f * P);   // z^p*d = DS * 2^(p*lg2(qz)), qz = z*2^11
    }
    if (i < n_out) out[i] = 0.0f;
    if (i < n) {
        unsigned q = __float2uint_rn(z[i] * ZSCALE);
        g_ztab[i] = (uint16_t)(q > 65535u ? 65535u : q);
    }
}

template<bool FITS>
__global__ void __launch_bounds__(NTHREADS, 1)
edge_kernel(const float* __restrict__ cut, const float* __restrict__ len,
            const int* __restrict__ snd, const int* __restrict__ rcv,
            float* __restrict__ out, int E, int tn, int zb) {
    extern __shared__ __align__(16) char sm[];
    uint16_t* s_z = (uint16_t*)sm;
    float2*   s_y = (float2*)(sm + zb);
    float2*   s_g = s_y + YLUT_N;

    // Stage: node table (zb bytes) + LUTs (12288B), uint4-vectorized.
    {
        uint4* dst = (uint4*)sm;
        const uint4* src = (const uint4*)g_ztab;
        int nv = zb >> 4;
        for (int i = threadIdx.x; i < nv; i += NTHREADS) dst[i] = src[i];
        uint4* dl = (uint4*)(sm + zb);
        const uint4* sl = (const uint4*)g_lut;
        for (int i = threadIdx.x; i < (LUT_BYTES >> 4); i += NTHREADS) dl[i] = sl[i];
    }
    __syncthreads();

    const float P  = g_par[0], DS = g_par[1];

    const int nq = (E + 3) >> 2;
    const int stride = gridDim.x * NTHREADS;
    int q = blockIdx.x * NTHREADS + threadIdx.x;
    if (q >= nq) return;

    // ── Software pipeline: streaming loads for quad i+stride are issued
    //    before the math of quad i, hiding the ~600cyc DRAM latency.
    float4 Lv, Cv; int4 Sv, Rv;
    load_quad(q << 2, E, cut, len, snd, rcv, Lv, Cv, Sv, Rv);

    while (true) {
        int qn = q + stride;
        float4 Ln, Cn; int4 Sn, Rn;
        bool have_next = qn < nq;
        if (have_next) load_quad(qn << 2, E, cut, len, snd, rcv, Ln, Cn, Sn, Rn);

        const float* lp = &Lv.x; const float* cp = &Cv.x;
        const int* sp = &Sv.x; const int* rp = &Rv.x;

        // ── Phase A: unconditional smem gathers (indices always valid).
        float QS[4], QR[4];
#pragma unroll
        for (int k = 0; k < 4; k++) {
            int s = sp[k], r = rp[k];
            unsigned qs, qr;
            if (FITS) {
                qs = (unsigned)s_z[s];
                qr = (unsigned)s_z[r];
            } else {
                qs = (s < tn) ? (unsigned)s_z[s] : (unsigned)g_ztab[s];
                qr = (r < tn) ? (unsigned)s_z[r] : (unsigned)g_ztab[r];
            }
            QS[k] = (float)qs;
            QR[k] = (float)qr;
        }

        // ── Phase B: branch-free LUT + 4-MUFU math; only the RED is predicated.
#pragma unroll
        for (int k = 0; k < 4; k++) {
            float L = lp[k];

            // g = w(L)/L via LUT over [0.5, 1.5)
            float fg = (L - 0.5f) * (float)GLUT_N;
            fg = fminf(fmaxf(fg, 0.0f), (float)(GLUT_N - 1));
            int ig = (int)fg; float rg = fg - (float)ig;
            float2 G = s_g[ig];
            float g = fmaf(G.y, rg, G.x);

            // t = L * DS * (2^(P*lg2 qs) + 2^(P*lg2 qr))
            float zps = ex2f(P * lg2f(QS[k]));
            float zpr = ex2f(P * lg2f(QR[k]));
            float t = L * DS * (zps + zpr);

            // y(t) via LUT over [0, 16]
            float ft = t * ((float)YLUT_N / YLUT_TMAX);
            ft = fminf(fmaxf(ft, 0.0f), (float)(YLUT_N - 1));
            int it = (int)ft; float rt = ft - (float)it;
            float2 Y = s_y[it];
            float y = fmaf(Y.y, rt, Y.x);

            float num = (KE_HALF / (ZSCALE * ZSCALE)) * cp[k] * (QS[k] * QR[k]);
            float val = num * g * y;

            if (L < 1.5f) atomicAdd(out + rp[k], val);
        }

        if (!have_next) break;
        q = qn;
        Lv = Ln; Cv = Cn; Sv = Sn; Rv = Rn;
    }
}

extern "C" void kernel_launch(void* const* d_in, const int* in_sizes, int n_in,
                              void* d_out, int out_size) {
    const float* z   = (const float*)d_in[0];
    const float* cut = (const float*)d_in[1];
    const int*   snd = (const int*)  d_in[2];
    const int*   rcv = (const int*)  d_in[3];
    const float* len = (const float*)d_in[4];

    int pb = n_in - 10;
    const float* a1 = (const float*)d_in[pb + 0];
    const float* a2 = (const float*)d_in[pb + 1];
    const float* a3 = (const float*)d_in[pb + 2];
    const float* a4 = (const float*)d_in[pb + 3];
    const float* c1 = (const float*)d_in[pb + 4];
    const float* c2 = (const float*)d_in[pb + 5];
    const float* c3 = (const float*)d_in[pb + 6];
    const float* c4 = (const float*)d_in[pb + 7];
    const float* pr = (const float*)d_in[pb + 8];
    const float* dr = (const float*)d_in[pb + 9];

    int N = in_sizes[0];
    int E = in_sizes[2];
    if (N > MAX_NODES) N = MAX_NODES;

    float* out = (float*)d_out;

    int cover = (N > out_size) ? N : out_size;
    node_kernel<<<(cover + 255) / 256, 256>>>(z, pr, dr, a1, a2, a3, a4,
                                              c1, c2, c3, c4, out, N, out_size);

    int tn = (N < SMEM_CAP_NODES) ? N : SMEM_CAP_NODES;
    int zb = (tn * 2 + 15) & ~15;          // staged table bytes, 16B-aligned
    int smem = zb + LUT_BYTES;

    static int nsm = 0;
    if (nsm == 0) {
        cudaDeviceGetAttribute(&nsm, cudaDevAttrMultiProcessorCount, 0);
        if (nsm <= 0) nsm = 148;
        cudaFuncSetAttribute(edge_kernel<true>,
                             cudaFuncAttributeMaxDynamicSharedMemorySize,
                             SMEM_CAP_NODES * 2 + 16 + LUT_BYTES);
        cudaFuncSetAttribute(edge_kernel<false>,
                             cudaFuncAttributeMaxDynamicSharedMemorySize,
                             SMEM_CAP_NODES * 2 + 16 + LUT_BYTES);
    }
    if (N <= SMEM_CAP_NODES)
        edge_kernel<true><<<nsm, NTHREADS, smem>>>(cut, len, snd, rcv, out, E, tn, zb);
    else
        edge_kernel<false><<<nsm, NTHREADS, smem>>>(cut, len, snd, rcv, out, E, tn, zb);
}